// round 1
// baseline (speedup 1.0000x reference)
#include <cuda_runtime.h>

// BilinearInterpolation: B=16, H=W=512, C=16 fp32.
// Affine grid-sample with diagonal theta: x depends only on out-col, y only on out-row.
// One thread per (batch, oy, ox, channel-quad) -> float4 gathers + coalesced float4 store.

#define BB 16
#define HH 512
#define WW 512
#define CC 16
#define QPP 4   // float4 quads per pixel (C/4)

__global__ void __launch_bounds__(256)
bilinear_kernel(const float* __restrict__ X,
                const float* __restrict__ scale,
                const float* __restrict__ translate,
                float4* __restrict__ out)
{
    const int i = blockIdx.x * blockDim.x + threadIdx.x;
    // i in [0, 16*512*512*4)
    const int q  = i & 3;           // channel quad
    const int ox = (i >> 2)  & 511; // out col
    const int oy = (i >> 11) & 511; // out row
    const int b  = i >> 20;         // batch

    const float s  = __ldg(&scale[b]);
    const float tx = __ldg(&translate[2 * b]);
    const float ty = __ldg(&translate[2 * b + 1]);

    // xc = linspace(-1,1,512)[ox] = -1 + ox * 2/511
    const float xc = fmaf((float)ox, 2.0f / 511.0f, -1.0f);
    const float yc = fmaf((float)oy, 2.0f / 511.0f, -1.0f);

    // sg = s*c + t ;  coord = 0.5*(sg+1)*dim
    const float x = 0.5f * (fmaf(s, xc, tx) + 1.0f) * (float)WW;
    const float y = 0.5f * (fmaf(s, yc, ty) + 1.0f) * (float)HH;

    // Reference uses astype(int32): truncation toward zero, THEN clamp.
    int x0 = (int)x;
    int y0 = (int)y;
    int x1 = x0 + 1;
    int y1 = y0 + 1;
    x0 = min(max(x0, 0), WW - 1);
    x1 = min(max(x1, 0), WW - 1);
    y0 = min(max(y0, 0), HH - 1);
    y1 = min(max(y1, 0), HH - 1);

    // Weights from clamped integer coords vs unclamped float coords (matches ref).
    const float x0f = (float)x0, x1f = (float)x1;
    const float y0f = (float)y0, y1f = (float)y1;
    const float dx1 = x1f - x, dx0 = x - x0f;
    const float dy1 = y1f - y, dy0 = y - y0f;
    const float wa = dx1 * dy1;
    const float wb = dx1 * dy0;
    const float wc = dx0 * dy1;
    const float wd = dx0 * dy0;

    // X viewed as float4: pixel (b,y,x) quad q at ((b*H + y)*W + x)*4 + q
    const float4* __restrict__ Xb =
        reinterpret_cast<const float4*>(X) + ((size_t)b * (HH * WW) * QPP) + q;

    const float4 pa = __ldg(&Xb[(size_t)(y0 * WW + x0) * QPP]);
    const float4 pb = __ldg(&Xb[(size_t)(y1 * WW + x0) * QPP]);
    const float4 pc = __ldg(&Xb[(size_t)(y0 * WW + x1) * QPP]);
    const float4 pd = __ldg(&Xb[(size_t)(y1 * WW + x1) * QPP]);

    float4 o;
    o.x = fmaf(wa, pa.x, fmaf(wb, pb.x, fmaf(wc, pc.x, wd * pd.x)));
    o.y = fmaf(wa, pa.y, fmaf(wb, pb.y, fmaf(wc, pc.y, wd * pd.y)));
    o.z = fmaf(wa, pa.z, fmaf(wb, pb.z, fmaf(wc, pc.z, wd * pd.z)));
    o.w = fmaf(wa, pa.w, fmaf(wb, pb.w, fmaf(wc, pc.w, wd * pd.w)));

    out[i] = o;
}

extern "C" void kernel_launch(void* const* d_in, const int* in_sizes, int n_in,
                              void* d_out, int out_size)
{
    const float* X         = (const float*)d_in[0];
    const float* scale     = (const float*)d_in[1];
    const float* translate = (const float*)d_in[2];
    float4* out            = (float4*)d_out;

    const int total_quads = BB * HH * WW * QPP;   // 16,777,216
    const int threads = 256;
    const int blocks = total_quads / threads;     // 65,536
    bilinear_kernel<<<blocks, threads>>>(X, scale, translate, out);
}